// round 1
// baseline (speedup 1.0000x reference)
#include <cuda_runtime.h>
#include <math.h>

#define Bsz 4
#define Ssz 2048
#define DVs 1024
#define Hs  16
#define Dhd 64
#define Tsz 64
#define DTs 768

// Scratch (allocation-free): q,k,v in [B,H,S,Dh] head-major layout
__device__ float g_q[Bsz * Hs * Ssz * Dhd];
__device__ float g_k[Bsz * Hs * Ssz * Dhd];
__device__ float g_v[Bsz * Hs * Ssz * Dhd];
__device__ float g_gate[2][Bsz * DVs];

// ---------------------------------------------------------------------------
// Kernel 1: masked-mean pool + dynamic gates (1 + sigmoid(pool @ Wd + bd))
// grid (B, 2), 256 threads
// ---------------------------------------------------------------------------
__global__ void gates_kernel(const float* __restrict__ txt,
                             const float* __restrict__ tmask,
                             const float* __restrict__ Wdq, const float* __restrict__ bdq,
                             const float* __restrict__ Wdk, const float* __restrict__ bdk) {
    int b = blockIdx.x;
    int which = blockIdx.y;
    const float* W    = which ? Wdk : Wdq;
    const float* bias = which ? bdk : bdq;

    __shared__ float pool[DTs];
    __shared__ float msum_s;
    int tid = threadIdx.x;

    if (tid == 0) {
        float ms = 0.f;
        for (int t = 0; t < Tsz; t++) ms += tmask[b * Tsz + t];
        msum_s = ms;
    }
    for (int d = tid; d < DTs; d += blockDim.x) {
        float acc = 0.f;
        for (int t = 0; t < Tsz; t++)
            acc += txt[(b * Tsz + t) * DTs + d] * tmask[b * Tsz + t];
        pool[d] = acc;
    }
    __syncthreads();
    float inv = 1.f / msum_s;

    for (int n = tid; n < DVs; n += blockDim.x) {
        float dot = 0.f;
        for (int d = 0; d < DTs; d++)
            dot += pool[d] * W[d * DVs + n];
        float x = bias[n] + dot * inv;
        g_gate[which][b * DVs + n] = 1.f + 1.f / (1.f + expf(-x));
    }
}

// ---------------------------------------------------------------------------
// Kernel 2: QKV projection GEMM. grid (DV/64, M/64, 3), 256 threads.
// Y = X @ W + b, epilogue applies gate (q,k) and writes [B,H,S,Dh] layout.
// ---------------------------------------------------------------------------
__global__ void qkv_kernel(const float* __restrict__ X,
                           const float* __restrict__ Wq, const float* __restrict__ bq,
                           const float* __restrict__ Wk, const float* __restrict__ bk,
                           const float* __restrict__ Wv, const float* __restrict__ bv) {
    int sel = blockIdx.z;
    const float* W    = sel == 0 ? Wq : (sel == 1 ? Wk : Wv);
    const float* bias = sel == 0 ? bq : (sel == 1 ? bk : bv);
    float* dst        = sel == 0 ? g_q : (sel == 1 ? g_k : g_v);
    const float* gate = sel == 0 ? g_gate[0] : (sel == 1 ? g_gate[1] : nullptr);

    __shared__ float Xs[16][68];   // [k][m]
    __shared__ float Ws[16][68];   // [k][n]

    int tid = threadIdx.x;
    int tx = tid & 15, ty = tid >> 4;
    int m0 = blockIdx.y * 64, n0 = blockIdx.x * 64;

    float acc[4][4] = {};

    int lm = tid >> 2, lc4 = tid & 3;     // X loader: row lm, k-chunk lc4
    int lk = tid >> 4, ln4 = tid & 15;    // W loader: k-row lk, n-chunk ln4

    for (int k0 = 0; k0 < DVs; k0 += 16) {
        float4 xv = *(const float4*)&X[(size_t)(m0 + lm) * DVs + k0 + lc4 * 4];
        Xs[lc4 * 4 + 0][lm] = xv.x;
        Xs[lc4 * 4 + 1][lm] = xv.y;
        Xs[lc4 * 4 + 2][lm] = xv.z;
        Xs[lc4 * 4 + 3][lm] = xv.w;
        *(float4*)&Ws[lk][ln4 * 4] =
            *(const float4*)&W[(size_t)(k0 + lk) * DVs + n0 + ln4 * 4];
        __syncthreads();

        #pragma unroll
        for (int kk = 0; kk < 16; kk++) {
            float4 a  = *(float4*)&Xs[kk][ty * 4];
            float4 bb = *(float4*)&Ws[kk][tx * 4];
            float av[4] = {a.x, a.y, a.z, a.w};
            float bw[4] = {bb.x, bb.y, bb.z, bb.w};
            #pragma unroll
            for (int i = 0; i < 4; i++)
                #pragma unroll
                for (int j = 0; j < 4; j++)
                    acc[i][j] += av[i] * bw[j];
        }
        __syncthreads();
    }

    // epilogue: bias + gate, write head-major [B,H,S,Dh]
    int n  = n0 + tx * 4;
    int h  = n >> 6, dd = n & 63;
    #pragma unroll
    for (int i = 0; i < 4; i++) {
        int m = m0 + ty * 4 + i;
        int b = m >> 11, s = m & 2047;
        float4 o;
        float* po = (float*)&o;
        #pragma unroll
        for (int j = 0; j < 4; j++) {
            float v = acc[i][j] + bias[n + j];
            if (gate) v *= gate[b * DVs + n + j];
            po[j] = v;
        }
        *(float4*)&dst[((((size_t)b * Hs + h) * Ssz) + s) * Dhd + dd] = o;
    }
}

// ---------------------------------------------------------------------------
// Kernel 3: flash attention. grid (S/64, H, B), 256 threads (16x16).
// Q/K/P transposed in smem ([d][row], stride 68) for conflict-free float4.
// ---------------------------------------------------------------------------
__device__ __forceinline__ float rmax16(float v) {
    #pragma unroll
    for (int o = 8; o; o >>= 1) v = fmaxf(v, __shfl_xor_sync(0xffffffffu, v, o));
    return v;
}
__device__ __forceinline__ float rsum16(float v) {
    #pragma unroll
    for (int o = 8; o; o >>= 1) v += __shfl_xor_sync(0xffffffffu, v, o);
    return v;
}

__global__ void attn_kernel(const float* __restrict__ amask, float* __restrict__ out) {
    extern __shared__ float sm[];
    float (*Qs)[68] = (float(*)[68])(sm);              // [d][qrow]
    float (*Ks)[68] = (float(*)[68])(sm + 64 * 68);    // [d][krow]
    float (*Vs)[68] = (float(*)[68])(sm + 2 * 64 * 68);// [krow][d]
    float (*Ps)[68] = (float(*)[68])(sm + 3 * 64 * 68);// [krow][qrow]

    int q0 = blockIdx.x * 64;
    int h = blockIdx.y, b = blockIdx.z;
    int tid = threadIdx.x;
    int tx = tid & 15, ty = tid >> 4;

    const float* qbase = g_q + ((size_t)(b * Hs + h)) * Ssz * Dhd;
    const float* kbase = g_k + ((size_t)(b * Hs + h)) * Ssz * Dhd;
    const float* vbase = g_v + ((size_t)(b * Hs + h)) * Ssz * Dhd;
    const float scale = 0.125f;  // 1/sqrt(64)

    // load Q tile transposed, pre-scaled
    #pragma unroll
    for (int it = 0; it < 4; it++) {
        int idx = tid + it * 256;
        int r = idx >> 4, c4 = idx & 15;
        float4 v = *(const float4*)&qbase[(size_t)(q0 + r) * Dhd + c4 * 4];
        Qs[c4 * 4 + 0][r] = v.x * scale;
        Qs[c4 * 4 + 1][r] = v.y * scale;
        Qs[c4 * 4 + 2][r] = v.z * scale;
        Qs[c4 * 4 + 3][r] = v.w * scale;
    }

    float m_i[4], l_i[4], O[4][4];
    #pragma unroll
    for (int i = 0; i < 4; i++) {
        m_i[i] = -1e30f; l_i[i] = 0.f;
        #pragma unroll
        for (int j = 0; j < 4; j++) O[i][j] = 0.f;
    }

    for (int kt = 0; kt < Ssz / 64; kt++) {
        int kr0 = kt * 64;
        // load K (transposed) and V (natural)
        #pragma unroll
        for (int it = 0; it < 4; it++) {
            int idx = tid + it * 256;
            int r = idx >> 4, c4 = idx & 15;
            float4 v = *(const float4*)&kbase[(size_t)(kr0 + r) * Dhd + c4 * 4];
            Ks[c4 * 4 + 0][r] = v.x;
            Ks[c4 * 4 + 1][r] = v.y;
            Ks[c4 * 4 + 2][r] = v.z;
            Ks[c4 * 4 + 3][r] = v.w;
            *(float4*)&Vs[r][c4 * 4] =
                *(const float4*)&vbase[(size_t)(kr0 + r) * Dhd + c4 * 4];
        }
        __syncthreads();

        // scores: S = (Q*scale) K^T  (thread owns 4x4 of 64x64)
        float s[4][4] = {};
        #pragma unroll 8
        for (int d = 0; d < 64; d++) {
            float4 qv = *(float4*)&Qs[d][ty * 4];
            float4 kv = *(float4*)&Ks[d][tx * 4];
            float qa[4] = {qv.x, qv.y, qv.z, qv.w};
            float ka[4] = {kv.x, kv.y, kv.z, kv.w};
            #pragma unroll
            for (int i = 0; i < 4; i++)
                #pragma unroll
                for (int j = 0; j < 4; j++)
                    s[i][j] += qa[i] * ka[j];
        }
        // additive mask [B,1,1,S]
        #pragma unroll
        for (int j = 0; j < 4; j++) {
            float mk = amask[b * Ssz + kr0 + tx * 4 + j];
            #pragma unroll
            for (int i = 0; i < 4; i++) s[i][j] += mk;
        }

        // online softmax per score-row; write P transposed
        #pragma unroll
        for (int i = 0; i < 4; i++) {
            float rm = fmaxf(fmaxf(s[i][0], s[i][1]), fmaxf(s[i][2], s[i][3]));
            rm = rmax16(rm);
            float mnew  = fmaxf(m_i[i], rm);
            float alpha = __expf(m_i[i] - mnew);
            float p0 = __expf(s[i][0] - mnew);
            float p1 = __expf(s[i][1] - mnew);
            float p2 = __expf(s[i][2] - mnew);
            float p3 = __expf(s[i][3] - mnew);
            float rs = rsum16(p0 + p1 + p2 + p3);
            l_i[i] = l_i[i] * alpha + rs;
            m_i[i] = mnew;
            #pragma unroll
            for (int j = 0; j < 4; j++) O[i][j] *= alpha;
            Ps[tx * 4 + 0][ty * 4 + i] = p0;
            Ps[tx * 4 + 1][ty * 4 + i] = p1;
            Ps[tx * 4 + 2][ty * 4 + i] = p2;
            Ps[tx * 4 + 3][ty * 4 + i] = p3;
        }
        __syncthreads();

        // O += P @ V
        #pragma unroll 8
        for (int j = 0; j < 64; j++) {
            float4 pv = *(float4*)&Ps[j][ty * 4];
            float4 vv = *(float4*)&Vs[j][tx * 4];
            float pa[4] = {pv.x, pv.y, pv.z, pv.w};
            float va[4] = {vv.x, vv.y, vv.z, vv.w};
            #pragma unroll
            for (int i = 0; i < 4; i++)
                #pragma unroll
                for (int c = 0; c < 4; c++)
                    O[i][c] += pa[i] * va[c];
        }
        __syncthreads();
    }

    // epilogue: normalize, write [B,S,H,Dh]
    #pragma unroll
    for (int i = 0; i < 4; i++) {
        float invl = 1.f / l_i[i];
        int row = q0 + ty * 4 + i;
        float4 o = {O[i][0] * invl, O[i][1] * invl, O[i][2] * invl, O[i][3] * invl};
        *(float4*)&out[(((size_t)b * Ssz + row) * Hs + h) * Dhd + tx * 4] = o;
    }
}

// ---------------------------------------------------------------------------
extern "C" void kernel_launch(void* const* d_in, const int* in_sizes, int n_in,
                              void* d_out, int out_size) {
    const float* X     = (const float*)d_in[0];   // hidden_states [B,S,DV]
    const float* amask = (const float*)d_in[1];   // attention_mask [B,1,1,S]
    const float* txt   = (const float*)d_in[2];   // txt_embedding [B,T,DT]
    const float* tmask = (const float*)d_in[3];   // txt_attention_mask [B,T,1]
    const float* Wq  = (const float*)d_in[4];
    const float* bq  = (const float*)d_in[5];
    const float* Wk  = (const float*)d_in[6];
    const float* bk  = (const float*)d_in[7];
    const float* Wv  = (const float*)d_in[8];
    const float* bv  = (const float*)d_in[9];
    const float* Wdq = (const float*)d_in[10];
    const float* bdq = (const float*)d_in[11];
    const float* Wdk = (const float*)d_in[12];
    const float* bdk = (const float*)d_in[13];
    float* out = (float*)d_out;

    // 1) gates
    gates_kernel<<<dim3(Bsz, 2), 256>>>(txt, tmask, Wdq, bdq, Wdk, bdk);

    // 2) QKV projection (+bias, +gate, head-major layout)
    dim3 ggrid(DVs / 64, (Bsz * Ssz) / 64, 3);
    qkv_kernel<<<ggrid, 256>>>(X, Wq, bq, Wk, bk, Wv, bv);

    // 3) flash attention
    int smem = 4 * 64 * 68 * (int)sizeof(float);  // 69632 B
    cudaFuncSetAttribute(attn_kernel, cudaFuncAttributeMaxDynamicSharedMemorySize, smem);
    attn_kernel<<<dim3(Ssz / 64, Hs, Bsz), 256, smem>>>(amask, out);
}

// round 2
// speedup vs baseline: 3.1640x; 3.1640x over previous
#include <cuda_runtime.h>
#include <math.h>

#define Bsz 4
#define Ssz 2048
#define DVs 1024
#define Hs  16
#define Dhd 64
#define Tsz 64
#define DTs 768

// Scratch (allocation-free): q,k,v in [B,H,S,Dh] head-major layout
__device__ float g_q[Bsz * Hs * Ssz * Dhd];
__device__ float g_k[Bsz * Hs * Ssz * Dhd];
__device__ float g_v[Bsz * Hs * Ssz * Dhd];
__device__ float g_gate[2][Bsz * DVs];

// ---------------------------------------------------------------------------
// helpers: tf32 conversion + m16n8k8 tf32 mma
// ---------------------------------------------------------------------------
__device__ __forceinline__ unsigned f2tf32(float x) {
    unsigned u;
    asm("cvt.rna.tf32.f32 %0, %1;" : "=r"(u) : "f"(x));
    return u;
}

__device__ __forceinline__ void mma_tf32(float* c, const unsigned* a, const unsigned* b) {
    asm volatile(
        "mma.sync.aligned.m16n8k8.row.col.f32.tf32.tf32.f32 "
        "{%0,%1,%2,%3}, {%4,%5,%6,%7}, {%8,%9}, {%0,%1,%2,%3};"
        : "+f"(c[0]), "+f"(c[1]), "+f"(c[2]), "+f"(c[3])
        : "r"(a[0]), "r"(a[1]), "r"(a[2]), "r"(a[3]), "r"(b[0]), "r"(b[1]));
}

__device__ __forceinline__ float shsel(float v0, float v1, int src, int odd) {
    float a = __shfl_sync(0xffffffffu, v0, src);
    float b = __shfl_sync(0xffffffffu, v1, src);
    return odd ? b : a;
}

// ---------------------------------------------------------------------------
// Kernel 1: gates.  grid (B, 2, 8), 128 threads. Each block: 128 outputs.
// ---------------------------------------------------------------------------
__global__ void gates_kernel(const float* __restrict__ txt,
                             const float* __restrict__ tmask,
                             const float* __restrict__ Wdq, const float* __restrict__ bdq,
                             const float* __restrict__ Wdk, const float* __restrict__ bdk) {
    int b = blockIdx.x, which = blockIdx.y, chunk = blockIdx.z;
    const float* W    = which ? Wdk : Wdq;
    const float* bias = which ? bdk : bdq;

    __shared__ float pool[DTs];
    __shared__ float tm[Tsz];
    int tid = threadIdx.x;

    if (tid < Tsz) tm[tid] = tmask[b * Tsz + tid];
    __syncthreads();

    float msum = 0.f;
    #pragma unroll 8
    for (int t = 0; t < Tsz; t++) msum += tm[t];

    for (int d = tid; d < DTs; d += 128) {
        float acc = 0.f;
        #pragma unroll 8
        for (int t = 0; t < Tsz; t++)
            acc += txt[(b * Tsz + t) * DTs + d] * tm[t];
        pool[d] = acc;
    }
    __syncthreads();

    int n = chunk * 128 + tid;
    float dot = 0.f;
    #pragma unroll 8
    for (int d = 0; d < DTs; d++)
        dot += pool[d] * W[d * DVs + n];
    float x = bias[n] + dot / msum;
    g_gate[which][b * DVs + n] = 1.f + 1.f / (1.f + expf(-x));
}

// ---------------------------------------------------------------------------
// Kernel 2: QKV projection, tf32 mma. BM=128, BN=128, BK=16, 256 thr/8 warps.
// Warp tile 64x32 (warp_m = w&1, warp_n = w>>1). grid (8, 64, 3).
// ---------------------------------------------------------------------------
__global__ void __launch_bounds__(256) qkv_kernel(
        const float* __restrict__ X,
        const float* __restrict__ Wq, const float* __restrict__ bq,
        const float* __restrict__ Wk, const float* __restrict__ bk,
        const float* __restrict__ Wv, const float* __restrict__ bv) {
    int sel = blockIdx.z;
    const float* W    = sel == 0 ? Wq : (sel == 1 ? Wk : Wv);
    const float* bias = sel == 0 ? bq : (sel == 1 ? bk : bv);
    float* dst        = sel == 0 ? g_q : (sel == 1 ? g_k : g_v);

    __shared__ unsigned Xs[128][20];   // [m][k], stride 20: bank-conflict-free A reads
    __shared__ unsigned Ws[16][136];   // [k][n], stride 136: conflict-free B reads

    int tid = threadIdx.x;
    int w = tid >> 5, lane = tid & 31;
    int tg = lane & 3, gid = lane >> 2;
    int warp_m = (w & 1) * 64, warp_n = (w >> 1) * 32;
    int m0 = blockIdx.y * 128, n0 = blockIdx.x * 128;

    float acc[4][4][4] = {};

    // loader indices
    int xr = tid >> 1, xc = (tid & 1) * 8;     // X: row xr, 8 floats at xc
    int wk = tid >> 4, wn = (tid & 15) * 8;    // W: row wk, 8 floats at wn

    for (int k0 = 0; k0 < DVs; k0 += 16) {
        float4 xv0 = *(const float4*)&X[(size_t)(m0 + xr) * DVs + k0 + xc];
        float4 xv1 = *(const float4*)&X[(size_t)(m0 + xr) * DVs + k0 + xc + 4];
        float4 wv0 = *(const float4*)&W[(size_t)(k0 + wk) * DVs + n0 + wn];
        float4 wv1 = *(const float4*)&W[(size_t)(k0 + wk) * DVs + n0 + wn + 4];
        __syncthreads();
        {
            uint4 u0 = {f2tf32(xv0.x), f2tf32(xv0.y), f2tf32(xv0.z), f2tf32(xv0.w)};
            uint4 u1 = {f2tf32(xv1.x), f2tf32(xv1.y), f2tf32(xv1.z), f2tf32(xv1.w)};
            *(uint4*)&Xs[xr][xc] = u0;
            *(uint4*)&Xs[xr][xc + 4] = u1;
            uint4 t0 = {f2tf32(wv0.x), f2tf32(wv0.y), f2tf32(wv0.z), f2tf32(wv0.w)};
            uint4 t1 = {f2tf32(wv1.x), f2tf32(wv1.y), f2tf32(wv1.z), f2tf32(wv1.w)};
            *(uint4*)&Ws[wk][wn] = t0;
            *(uint4*)&Ws[wk][wn + 4] = t1;
        }
        __syncthreads();

        #pragma unroll
        for (int ks = 0; ks < 2; ks++) {
            int kb = ks * 8;
            unsigned a[4][4];
            #pragma unroll
            for (int mi = 0; mi < 4; mi++) {
                int r = warp_m + mi * 16 + gid;
                a[mi][0] = Xs[r][kb + tg];
                a[mi][1] = Xs[r + 8][kb + tg];
                a[mi][2] = Xs[r][kb + tg + 4];
                a[mi][3] = Xs[r + 8][kb + tg + 4];
            }
            #pragma unroll
            for (int nj = 0; nj < 4; nj++) {
                unsigned bfr[2];
                bfr[0] = Ws[kb + tg][warp_n + nj * 8 + gid];
                bfr[1] = Ws[kb + tg + 4][warp_n + nj * 8 + gid];
                #pragma unroll
                for (int mi = 0; mi < 4; mi++)
                    mma_tf32(acc[mi][nj], a[mi], bfr);
            }
        }
    }

    // epilogue: bias + gate, write head-major [B,H,S,Dh]
    const float* gate = sel == 0 ? g_gate[0] : (sel == 1 ? g_gate[1] : nullptr);
    #pragma unroll
    for (int nj = 0; nj < 4; nj++) {
        int col = n0 + warp_n + nj * 8 + 2 * tg;
        int h = col >> 6, dd = col & 63;
        float b0 = bias[col], b1 = bias[col + 1];
        #pragma unroll
        for (int mi = 0; mi < 4; mi++) {
            int r0 = m0 + warp_m + mi * 16 + gid;
            int bb = r0 >> 11;
            int s0 = r0 & 2047;
            float g0 = 1.f, g1 = 1.f;
            if (sel < 2) {
                g0 = gate[bb * DVs + col];
                g1 = gate[bb * DVs + col + 1];
            }
            float2 o0 = {(acc[mi][nj][0] + b0) * g0, (acc[mi][nj][1] + b1) * g1};
            float2 o1 = {(acc[mi][nj][2] + b0) * g0, (acc[mi][nj][3] + b1) * g1};
            size_t base = (((size_t)bb * Hs + h) * Ssz);
            *(float2*)&dst[(base + s0) * Dhd + dd] = o0;
            *(float2*)&dst[(base + s0 + 8) * Dhd + dd] = o1;
        }
    }
}

// ---------------------------------------------------------------------------
// Kernel 3: flash attention, tf32 mma. BQ=128, KV tile 64, 256 thr/8 warps.
// Each warp owns 16 full q-rows (no cross-warp softmax). grid (16, H, B).
// ---------------------------------------------------------------------------
__global__ void __launch_bounds__(256, 2) attn_kernel(
        const float* __restrict__ amask, float* __restrict__ out) {
    extern __shared__ unsigned smattn[];
    unsigned (*Qs)[68] = (unsigned(*)[68])smattn;                       // [qrow][d]
    unsigned (*Ks)[68] = (unsigned(*)[68])(smattn + 128 * 68);          // [kvrow][d]
    unsigned (*Vs)[72] = (unsigned(*)[72])(smattn + 128 * 68 + 64 * 68);// [kvrow][d]

    int q0 = blockIdx.x * 128;
    int h = blockIdx.y, b = blockIdx.z;
    int tid = threadIdx.x;
    int w = tid >> 5, lane = tid & 31;
    int tg = lane & 3, gid = lane >> 2;
    int qr = w * 16;

    const float* qbase = g_q + ((size_t)(b * Hs + h)) * Ssz * Dhd;
    const float* kbase = g_k + ((size_t)(b * Hs + h)) * Ssz * Dhd;
    const float* vbase = g_v + ((size_t)(b * Hs + h)) * Ssz * Dhd;

    // load Q tile (pre-scaled by 1/sqrt(Dh))
    #pragma unroll
    for (int it = 0; it < 8; it++) {
        int idx = it * 256 + tid;
        int r = idx >> 4, c4 = (idx & 15) * 4;
        float4 v = *(const float4*)&qbase[(size_t)(q0 + r) * Dhd + c4];
        uint4 u = {f2tf32(v.x * 0.125f), f2tf32(v.y * 0.125f),
                   f2tf32(v.z * 0.125f), f2tf32(v.w * 0.125f)};
        *(uint4*)&Qs[r][c4] = u;
    }

    float o[8][4] = {};
    float m0 = -1e30f, m1 = -1e30f, l0 = 0.f, l1 = 0.f;

    int src0 = (lane & 28) | (tg >> 1);
    int src1 = src0 + 2;
    int odd = tg & 1;

    for (int kt = 0; kt < Ssz / 64; kt++) {
        int kr0 = kt * 64;
        __syncthreads();   // prev iter compute done (also covers Q visibility 1st iter)
        #pragma unroll
        for (int it = 0; it < 4; it++) {
            int idx = it * 256 + tid;
            int r = idx >> 4, c4 = (idx & 15) * 4;
            float4 kv = *(const float4*)&kbase[(size_t)(kr0 + r) * Dhd + c4];
            uint4 ku = {f2tf32(kv.x), f2tf32(kv.y), f2tf32(kv.z), f2tf32(kv.w)};
            *(uint4*)&Ks[r][c4] = ku;
            float4 vv = *(const float4*)&vbase[(size_t)(kr0 + r) * Dhd + c4];
            uint4 vu = {f2tf32(vv.x), f2tf32(vv.y), f2tf32(vv.z), f2tf32(vv.w)};
            *(uint4*)&Vs[r][c4] = vu;
        }
        __syncthreads();

        // S = Q K^T  (each warp: 16 rows x 64 kv)
        float s[8][4] = {};
        #pragma unroll
        for (int ks = 0; ks < 8; ks++) {
            int d0 = ks * 8;
            unsigned a[4];
            a[0] = Qs[qr + gid][d0 + tg];
            a[1] = Qs[qr + gid + 8][d0 + tg];
            a[2] = Qs[qr + gid][d0 + tg + 4];
            a[3] = Qs[qr + gid + 8][d0 + tg + 4];
            #pragma unroll
            for (int j = 0; j < 8; j++) {
                unsigned bfr[2];
                bfr[0] = Ks[j * 8 + gid][d0 + tg];
                bfr[1] = Ks[j * 8 + gid][d0 + tg + 4];
                mma_tf32(s[j], a, bfr);
            }
        }

        // additive mask + row max
        float mx0 = -1e30f, mx1 = -1e30f;
        #pragma unroll
        for (int j = 0; j < 8; j++) {
            int col = kr0 + j * 8 + 2 * tg;
            float mk0 = amask[b * Ssz + col];
            float mk1 = amask[b * Ssz + col + 1];
            s[j][0] += mk0; s[j][1] += mk1;
            s[j][2] += mk0; s[j][3] += mk1;
            mx0 = fmaxf(mx0, fmaxf(s[j][0], s[j][1]));
            mx1 = fmaxf(mx1, fmaxf(s[j][2], s[j][3]));
        }
        #pragma unroll
        for (int off = 1; off <= 2; off <<= 1) {
            mx0 = fmaxf(mx0, __shfl_xor_sync(0xffffffffu, mx0, off));
            mx1 = fmaxf(mx1, __shfl_xor_sync(0xffffffffu, mx1, off));
        }
        float mn0 = fmaxf(m0, mx0), mn1 = fmaxf(m1, mx1);
        float al0 = __expf(m0 - mn0), al1 = __expf(m1 - mn1);
        m0 = mn0; m1 = mn1;

        // P = exp(S - m), row sums
        float rs0 = 0.f, rs1 = 0.f;
        #pragma unroll
        for (int j = 0; j < 8; j++) {
            s[j][0] = __expf(s[j][0] - mn0);
            s[j][1] = __expf(s[j][1] - mn0);
            s[j][2] = __expf(s[j][2] - mn1);
            s[j][3] = __expf(s[j][3] - mn1);
            rs0 += s[j][0] + s[j][1];
            rs1 += s[j][2] + s[j][3];
        }
        #pragma unroll
        for (int off = 1; off <= 2; off <<= 1) {
            rs0 += __shfl_xor_sync(0xffffffffu, rs0, off);
            rs1 += __shfl_xor_sync(0xffffffffu, rs1, off);
        }
        l0 = l0 * al0 + rs0;
        l1 = l1 * al1 + rs1;

        #pragma unroll
        for (int dj = 0; dj < 8; dj++) {
            o[dj][0] *= al0; o[dj][1] *= al0;
            o[dj][2] *= al1; o[dj][3] *= al1;
        }

        // O += P V : convert C-frag P -> A-frag via shuffles (no smem round-trip)
        #pragma unroll
        for (int j = 0; j < 8; j++) {
            unsigned pa[4];
            pa[0] = f2tf32(shsel(s[j][0], s[j][1], src0, odd));
            pa[2] = f2tf32(shsel(s[j][0], s[j][1], src1, odd));
            pa[1] = f2tf32(shsel(s[j][2], s[j][3], src0, odd));
            pa[3] = f2tf32(shsel(s[j][2], s[j][3], src1, odd));
            #pragma unroll
            for (int dj = 0; dj < 8; dj++) {
                unsigned bfr[2];
                bfr[0] = Vs[j * 8 + tg][dj * 8 + gid];
                bfr[1] = Vs[j * 8 + tg + 4][dj * 8 + gid];
                mma_tf32(o[dj], pa, bfr);
            }
        }
    }

    // epilogue: normalize, write [B,S,H*Dh]
    float inv0 = 1.f / l0, inv1 = 1.f / l1;
    int r0 = q0 + qr + gid, r1 = r0 + 8;
    #pragma unroll
    for (int dj = 0; dj < 8; dj++) {
        int col = h * Dhd + dj * 8 + 2 * tg;
        float2 o0 = {o[dj][0] * inv0, o[dj][1] * inv0};
        float2 o1 = {o[dj][2] * inv1, o[dj][3] * inv1};
        *(float2*)&out[((size_t)b * Ssz + r0) * DVs + col] = o0;
        *(float2*)&out[((size_t)b * Ssz + r1) * DVs + col] = o1;
    }
}

// ---------------------------------------------------------------------------
extern "C" void kernel_launch(void* const* d_in, const int* in_sizes, int n_in,
                              void* d_out, int out_size) {
    const float* X     = (const float*)d_in[0];
    const float* amask = (const float*)d_in[1];
    const float* txt   = (const float*)d_in[2];
    const float* tmask = (const float*)d_in[3];
    const float* Wq  = (const float*)d_in[4];
    const float* bq  = (const float*)d_in[5];
    const float* Wk  = (const float*)d_in[6];
    const float* bk  = (const float*)d_in[7];
    const float* Wv  = (const float*)d_in[8];
    const float* bv  = (const float*)d_in[9];
    const float* Wdq = (const float*)d_in[10];
    const float* bdq = (const float*)d_in[11];
    const float* Wdk = (const float*)d_in[12];
    const float* bdk = (const float*)d_in[13];
    float* out = (float*)d_out;

    gates_kernel<<<dim3(Bsz, 2, 8), 128>>>(txt, tmask, Wdq, bdq, Wdk, bdk);

    qkv_kernel<<<dim3(DVs / 128, (Bsz * Ssz) / 128, 3), 256>>>(
        X, Wq, bq, Wk, bk, Wv, bv);

    int smem = (128 * 68 + 64 * 68 + 64 * 72) * (int)sizeof(unsigned);  // 70656 B
    cudaFuncSetAttribute(attn_kernel, cudaFuncAttributeMaxDynamicSharedMemorySize, smem);
    attn_kernel<<<dim3(Ssz / 128, Hs, Bsz), 256, smem>>>(amask, out);
}

// round 4
// speedup vs baseline: 3.7413x; 1.1825x over previous
#include <cuda_runtime.h>
#include <math.h>

#define Bsz 4
#define Ssz 2048
#define DVs 1024
#define Hs  16
#define Dhd 64
#define Tsz 64
#define DTs 768

// Scratch (allocation-free)
__device__ float g_q[Bsz * Hs * Ssz * Dhd];
__device__ float g_k[Bsz * Hs * Ssz * Dhd];
__device__ float g_v[Bsz * Hs * Ssz * Dhd];
__device__ float g_gate[2][Bsz * DVs];
__device__ float g_pool[Bsz][DTs];

// ---------------------------------------------------------------------------
// helpers
// ---------------------------------------------------------------------------
__device__ __forceinline__ unsigned f2tf32(float x) {
    unsigned u;
    asm("cvt.rna.tf32.f32 %0, %1;" : "=r"(u) : "f"(x));
    return u;
}

__device__ __forceinline__ void mma_tf32(float* c, const unsigned* a, const unsigned* b) {
    asm volatile(
        "mma.sync.aligned.m16n8k8.row.col.f32.tf32.tf32.f32 "
        "{%0,%1,%2,%3}, {%4,%5,%6,%7}, {%8,%9}, {%0,%1,%2,%3};"
        : "+f"(c[0]), "+f"(c[1]), "+f"(c[2]), "+f"(c[3])
        : "r"(a[0]), "r"(a[1]), "r"(a[2]), "r"(a[3]), "r"(b[0]), "r"(b[1]));
}

__device__ __forceinline__ float shsel(float v0, float v1, int src, int odd) {
    float a = __shfl_sync(0xffffffffu, v0, src);
    float b = __shfl_sync(0xffffffffu, v1, src);
    return odd ? b : a;
}

__device__ __forceinline__ unsigned smem_u32(const void* p) {
    return (unsigned)__cvta_generic_to_shared(p);
}
__device__ __forceinline__ void cp16(unsigned dst, const void* src) {
    asm volatile("cp.async.cg.shared.global [%0], [%1], 16;" :: "r"(dst), "l"(src));
}
#define CP_COMMIT() asm volatile("cp.async.commit_group;")
#define CP_WAIT(n)  asm volatile("cp.async.wait_group %0;" :: "n"(n))

// ---------------------------------------------------------------------------
// Kernel 1a: masked-mean pool. grid(B), 256 threads.
// ---------------------------------------------------------------------------
__global__ void pool_kernel(const float* __restrict__ txt,
                            const float* __restrict__ tmask) {
    int b = blockIdx.x, tid = threadIdx.x;
    __shared__ float tm[Tsz];
    if (tid < Tsz) tm[tid] = tmask[b * Tsz + tid];
    __syncthreads();
    float ms = 0.f;
    #pragma unroll 8
    for (int t = 0; t < Tsz; t++) ms += tm[t];
    float inv = 1.f / ms;
    for (int d = tid; d < DTs; d += 256) {
        float acc = 0.f;
        #pragma unroll 8
        for (int t = 0; t < Tsz; t++)
            acc += txt[(b * Tsz + t) * DTs + d] * tm[t];
        g_pool[b][d] = acc * inv;
    }
}

// ---------------------------------------------------------------------------
// Kernel 1b: gates GEMV, warp-per-output. grid(DV/8, 2, B), 256 threads.
// ---------------------------------------------------------------------------
__global__ void gates_kernel(const float* __restrict__ Wdq, const float* __restrict__ bdq,
                             const float* __restrict__ Wdk, const float* __restrict__ bdk) {
    int which = blockIdx.y, b = blockIdx.z;
    const float* W    = which ? Wdk : Wdq;
    const float* bias = which ? bdk : bdq;
    int w = threadIdx.x >> 5, lane = threadIdx.x & 31;
    int n = blockIdx.x * 8 + w;

    float dot = 0.f;
    #pragma unroll 6
    for (int d = lane; d < DTs; d += 32)
        dot += g_pool[b][d] * W[d * DVs + n];
    #pragma unroll
    for (int off = 16; off; off >>= 1)
        dot += __shfl_xor_sync(0xffffffffu, dot, off);
    if (lane == 0) {
        float x = dot + bias[n];
        g_gate[which][b * DVs + n] = 1.f + 1.f / (1.f + __expf(-x));
    }
}

// ---------------------------------------------------------------------------
// Kernel 2: QKV projection, tf32 mma, 3-stage cp.async pipeline.
// BM=128 BN=128 BK=16, 256 thr / 8 warps (warp tile 64x32). grid (8, 64, 3).
// smem stage: Xs[128][20] raw fp32 + Ws[16][136] raw fp32 (4736 floats).
// ---------------------------------------------------------------------------
#define QKV_STAGE 4736

__global__ void __launch_bounds__(256, 2) qkv_kernel(
        const float* __restrict__ X,
        const float* __restrict__ Wq, const float* __restrict__ bq,
        const float* __restrict__ Wk, const float* __restrict__ bk,
        const float* __restrict__ Wv, const float* __restrict__ bv) {
    extern __shared__ float smq[];
    int sel = blockIdx.z;
    const float* W    = sel == 0 ? Wq : (sel == 1 ? Wk : Wv);
    const float* bias = sel == 0 ? bq : (sel == 1 ? bk : bv);
    float* dst        = sel == 0 ? g_q : (sel == 1 ? g_k : g_v);

    int tid = threadIdx.x;
    int w = tid >> 5, lane = tid & 31;
    int tg = lane & 3, gid = lane >> 2;
    int warp_m = (w & 1) * 64, warp_n = (w >> 1) * 32;
    int m0 = blockIdx.y * 128, n0 = blockIdx.x * 128;

    // chunk mapping (2 X chunks + 2 W chunks per thread per stage)
    int xc0 = tid, xc1 = tid + 256;
    int xr0 = xc0 >> 2, xq0 = (xc0 & 3) * 4;
    int xr1 = xc1 >> 2, xq1 = (xc1 & 3) * 4;
    int wk0 = xc0 >> 5, wn0 = (xc0 & 31) * 4;
    int wk1 = xc1 >> 5, wn1 = (xc1 & 31) * 4;

    const float* Xb = X + (size_t)m0 * DVs;

    float acc[4][4][4] = {};

    // prologue: stages 0,1
    #pragma unroll
    for (int p = 0; p < 2; p++) {
        float* Xs = smq + p * QKV_STAGE;
        float* Ws = Xs + 128 * 20;
        int k0 = p * 16;
        cp16(smem_u32(Xs + xr0 * 20 + xq0), Xb + (size_t)xr0 * DVs + k0 + xq0);
        cp16(smem_u32(Xs + xr1 * 20 + xq1), Xb + (size_t)xr1 * DVs + k0 + xq1);
        cp16(smem_u32(Ws + wk0 * 136 + wn0), W + (size_t)(k0 + wk0) * DVs + n0 + wn0);
        cp16(smem_u32(Ws + wk1 * 136 + wn1), W + (size_t)(k0 + wk1) * DVs + n0 + wn1);
        CP_COMMIT();
    }

    int st = 0, st_ld = 2;
    for (int it = 0; it < 64; it++) {
        CP_WAIT(1);
        __syncthreads();

        if (it + 2 < 64) {
            float* Xs = smq + st_ld * QKV_STAGE;
            float* Ws = Xs + 128 * 20;
            int k0 = (it + 2) * 16;
            cp16(smem_u32(Xs + xr0 * 20 + xq0), Xb + (size_t)xr0 * DVs + k0 + xq0);
            cp16(smem_u32(Xs + xr1 * 20 + xq1), Xb + (size_t)xr1 * DVs + k0 + xq1);
            cp16(smem_u32(Ws + wk0 * 136 + wn0), W + (size_t)(k0 + wk0) * DVs + n0 + wn0);
            cp16(smem_u32(Ws + wk1 * 136 + wn1), W + (size_t)(k0 + wk1) * DVs + n0 + wn1);
        }
        CP_COMMIT();

        const float* Xs = smq + st * QKV_STAGE;
        const float* Ws = Xs + 128 * 20;

        #pragma unroll
        for (int ks = 0; ks < 2; ks++) {
            int kb = ks * 8;
            unsigned a[4][4];
            #pragma unroll
            for (int mi = 0; mi < 4; mi++) {
                int r = warp_m + mi * 16 + gid;
                a[mi][0] = f2tf32(Xs[r * 20 + kb + tg]);
                a[mi][1] = f2tf32(Xs[(r + 8) * 20 + kb + tg]);
                a[mi][2] = f2tf32(Xs[r * 20 + kb + tg + 4]);
                a[mi][3] = f2tf32(Xs[(r + 8) * 20 + kb + tg + 4]);
            }
            #pragma unroll
            for (int nj = 0; nj < 4; nj++) {
                unsigned bfr[2];
                bfr[0] = f2tf32(Ws[(kb + tg) * 136 + warp_n + nj * 8 + gid]);
                bfr[1] = f2tf32(Ws[(kb + tg + 4) * 136 + warp_n + nj * 8 + gid]);
                #pragma unroll
                for (int mi = 0; mi < 4; mi++)
                    mma_tf32(acc[mi][nj], a[mi], bfr);
            }
        }
        st = (st == 2) ? 0 : st + 1;
        st_ld = (st_ld == 2) ? 0 : st_ld + 1;
    }

    // epilogue: bias + gate, write head-major [B,H,S,Dh]
    const float* gate = sel == 0 ? g_gate[0] : (sel == 1 ? g_gate[1] : nullptr);
    #pragma unroll
    for (int nj = 0; nj < 4; nj++) {
        int col = n0 + warp_n + nj * 8 + 2 * tg;
        int h = col >> 6, dd = col & 63;
        float b0 = bias[col], b1 = bias[col + 1];
        #pragma unroll
        for (int mi = 0; mi < 4; mi++) {
            int r0 = m0 + warp_m + mi * 16 + gid;
            int bb = r0 >> 11;
            int s0 = r0 & 2047;
            float g0 = 1.f, g1 = 1.f;
            if (sel < 2) {
                g0 = gate[bb * DVs + col];
                g1 = gate[bb * DVs + col + 1];
            }
            float2 o0 = {(acc[mi][nj][0] + b0) * g0, (acc[mi][nj][1] + b1) * g1};
            float2 o1 = {(acc[mi][nj][2] + b0) * g0, (acc[mi][nj][3] + b1) * g1};
            size_t base = (((size_t)bb * Hs + h) * Ssz);
            *(float2*)&dst[(base + s0) * Dhd + dd] = o0;
            *(float2*)&dst[(base + s0 + 8) * Dhd + dd] = o1;
        }
    }
}

// ---------------------------------------------------------------------------
// Kernel 3: flash attention, tf32 mma, 2-stage cp.async K/V pipeline.
// BQ=128, KV tile 64, 256 thr / 8 warps (warp owns 16 q-rows). grid (16, H, B).
// smem: Qs[128][68] tf32 + 2 x (Kr[64][68] + Vr[64][72]) raw fp32.
// ---------------------------------------------------------------------------
#define ATTN_QS   (128 * 68)
#define ATTN_KST  (64 * 68)
#define ATTN_VST  (64 * 72)

__global__ void __launch_bounds__(256, 2) attn_kernel(
        const float* __restrict__ amask, float* __restrict__ out) {
    extern __shared__ float sma[];
    unsigned* Qs = (unsigned*)sma;                 // [128][68] tf32
    float* Kbuf = sma + ATTN_QS;                   // [2][64][68]
    float* Vbuf = sma + ATTN_QS + 2 * ATTN_KST;    // [2][64][72]

    int q0 = blockIdx.x * 128;
    int h = blockIdx.y, b = blockIdx.z;
    int tid = threadIdx.x;
    int w = tid >> 5, lane = tid & 31;
    int tg = lane & 3, gid = lane >> 2;
    int qr = w * 16;

    const float* qbase = g_q + ((size_t)(b * Hs + h)) * Ssz * Dhd;
    const float* kbase = g_k + ((size_t)(b * Hs + h)) * Ssz * Dhd;
    const float* vbase = g_v + ((size_t)(b * Hs + h)) * Ssz * Dhd;

    // cp.async chunk mapping for K/V: 4 chunks each per thread per tile
    int cr[4], cq[4];
    #pragma unroll
    for (int i = 0; i < 4; i++) {
        int c = tid + i * 256;
        cr[i] = c >> 4;
        cq[i] = (c & 15) * 4;
    }

    // load Q tile (pre-scaled), cvt to tf32
    #pragma unroll
    for (int it = 0; it < 8; it++) {
        int idx = it * 256 + tid;
        int r = idx >> 4, c4 = (idx & 15) * 4;
        float4 v = *(const float4*)&qbase[(size_t)(q0 + r) * Dhd + c4];
        uint4 u = {f2tf32(v.x * 0.125f), f2tf32(v.y * 0.125f),
                   f2tf32(v.z * 0.125f), f2tf32(v.w * 0.125f)};
        *(uint4*)&Qs[r * 68 + c4] = u;
    }

    // prologue: KV tiles 0,1
    #pragma unroll
    for (int p = 0; p < 2; p++) {
        float* Kr = Kbuf + p * ATTN_KST;
        float* Vr = Vbuf + p * ATTN_VST;
        int kr0 = p * 64;
        #pragma unroll
        for (int i = 0; i < 4; i++) {
            cp16(smem_u32(Kr + cr[i] * 68 + cq[i]), kbase + (size_t)(kr0 + cr[i]) * Dhd + cq[i]);
            cp16(smem_u32(Vr + cr[i] * 72 + cq[i]), vbase + (size_t)(kr0 + cr[i]) * Dhd + cq[i]);
        }
        CP_COMMIT();
    }

    float o[8][4] = {};
    float m0 = -1e30f, m1 = -1e30f, l0 = 0.f, l1 = 0.f;

    int src0 = (lane & 28) | (tg >> 1);
    int src1 = src0 + 2;
    int odd = tg & 1;

    for (int kt = 0; kt < Ssz / 64; kt++) {
        int kr0 = kt * 64;
        int buf = kt & 1;
        const float* Kr = Kbuf + buf * ATTN_KST;
        const float* Vr = Vbuf + buf * ATTN_VST;

        CP_WAIT(1);
        __syncthreads();

        // S = Q K^T
        float s[8][4] = {};
        #pragma unroll
        for (int ks = 0; ks < 8; ks++) {
            int d0 = ks * 8;
            unsigned a[4];
            a[0] = Qs[(qr + gid) * 68 + d0 + tg];
            a[1] = Qs[(qr + gid + 8) * 68 + d0 + tg];
            a[2] = Qs[(qr + gid) * 68 + d0 + tg + 4];
            a[3] = Qs[(qr + gid + 8) * 68 + d0 + tg + 4];
            #pragma unroll
            for (int j = 0; j < 8; j++) {
                unsigned bfr[2];
                bfr[0] = f2tf32(Kr[(j * 8 + gid) * 68 + d0 + tg]);
                bfr[1] = f2tf32(Kr[(j * 8 + gid) * 68 + d0 + tg + 4]);
                mma_tf32(s[j], a, bfr);
            }
        }

        // mask + online softmax
        float mx0 = -1e30f, mx1 = -1e30f;
        #pragma unroll
        for (int j = 0; j < 8; j++) {
            int col = kr0 + j * 8 + 2 * tg;
            float mk0 = amask[b * Ssz + col];
            float mk1 = amask[b * Ssz + col + 1];
            s[j][0] += mk0; s[j][1] += mk1;
            s[j][2] += mk0; s[j][3] += mk1;
            mx0 = fmaxf(mx0, fmaxf(s[j][0], s[j][1]));
            mx1 = fmaxf(mx1, fmaxf(s[j][2], s[j][3]));
        }
        #pragma unroll
        for (int off = 1; off <= 2; off <<= 1) {
            mx0 = fmaxf(mx0, __shfl_xor_sync(0xffffffffu, mx0, off));
            mx1 = fmaxf(mx1, __shfl_xor_sync(0xffffffffu, mx1, off));
        }
        float mn0 = fmaxf(m0, mx0), mn1 = fmaxf(m1, mx1);
        float al0 = __expf(m0 - mn0), al1 = __expf(m1 - mn1);
        m0 = mn0; m1 = mn1;

        float rs0 = 0.f, rs1 = 0.f;
        #pragma unroll
        for (int j = 0; j < 8; j++) {
            s[j][0] = __expf(s[j][0] - mn0);
            s[j][1] = __expf(s[j][1] - mn0);
            s[j][2] = __expf(s[j][2] - mn1);
            s[j][3] = __expf(s[j][3] - mn1);
            rs0 += s[j][0] + s[j][1];
            rs1 += s[j][2] + s[j][3];
        }
        #pragma unroll
        for (int off = 1; off <= 2; off <<= 1) {
            rs0 += __shfl_xor_sync(0xffffffffu, rs0, off);
            rs1 += __shfl_xor_sync(0xffffffffu, rs1, off);
        }
        l0 = l0 * al0 + rs0;
        l1 = l1 * al1 + rs1;

        #pragma unroll
        for (int dj = 0; dj < 8; dj++) {
            o[dj][0] *= al0; o[dj][1] *= al0;
            o[dj][2] *= al1; o[dj][3] *= al1;
        }

        // O += P V (P via shuffle C->A conversion)
        #pragma unroll
        for (int j = 0; j < 8; j++) {
            unsigned pa[4];
            pa[0] = f2tf32(shsel(s[j][0], s[j][1], src0, odd));
            pa[2] = f2tf32(shsel(s[j][0], s[j][1], src1, odd));
            pa[1] = f2tf32(shsel(s[j][2], s[j][3], src0, odd));
            pa[3] = f2tf32(shsel(s[j][2], s[j][3], src1, odd));
            #pragma unroll
            for (int dj = 0; dj < 8; dj++) {
                unsigned bfr[2];
                bfr[0] = f2tf32(Vr[(j * 8 + tg) * 72 + dj * 8 + gid]);
                bfr[1] = f2tf32(Vr[(j * 8 + tg + 4) * 72 + dj * 8 + gid]);
                mma_tf32(o[dj], pa, bfr);
            }
        }

        __syncthreads();
        // issue tile kt+2 into the buffer we just finished computing on
        if (kt + 2 < Ssz / 64) {
            float* Kw = Kbuf + buf * ATTN_KST;
            float* Vw = Vbuf + buf * ATTN_VST;
            int kn0 = (kt + 2) * 64;
            #pragma unroll
            for (int i = 0; i < 4; i++) {
                cp16(smem_u32(Kw + cr[i] * 68 + cq[i]), kbase + (size_t)(kn0 + cr[i]) * Dhd + cq[i]);
                cp16(smem_u32(Vw + cr[i] * 72 + cq[i]), vbase + (size_t)(kn0 + cr[i]) * Dhd + cq[i]);
            }
        }
        CP_COMMIT();
    }

    // epilogue
    float inv0 = 1.f / l0, inv1 = 1.f / l1;
    int r0 = q0 + qr + gid, r1 = r0 + 8;
    #pragma unroll
    for (int dj = 0; dj < 8; dj++) {
        int col = h * Dhd + dj * 8 + 2 * tg;
        float2 o0 = {o[dj][0] * inv0, o[dj][1] * inv0};
        float2 o1 = {o[dj][2] * inv1, o[dj][3] * inv1};
        *(float2*)&out[((size_t)b * Ssz + r0) * DVs + col] = o0;
        *(float2*)&out[((size_t)b * Ssz + r1) * DVs + col] = o1;
    }
}

// ---------------------------------------------------------------------------
extern "C" void kernel_launch(void* const* d_in, const int* in_sizes, int n_in,
                              void* d_out, int out_size) {
    const float* X     = (const float*)d_in[0];
    const float* amask = (const float*)d_in[1];
    const float* txt   = (const float*)d_in[2];
    const float* tmask = (const float*)d_in[3];
    const float* Wq  = (const float*)d_in[4];
    const float* bq  = (const float*)d_in[5];
    const float* Wk  = (const float*)d_in[6];
    const float* bk  = (const float*)d_in[7];
    const float* Wv  = (const float*)d_in[8];
    const float* bv  = (const float*)d_in[9];
    const float* Wdq = (const float*)d_in[10];
    const float* bdq = (const float*)d_in[11];
    const float* Wdk = (const float*)d_in[12];
    const float* bdk = (const float*)d_in[13];
    float* out = (float*)d_out;

    pool_kernel<<<Bsz, 256>>>(txt, tmask);
    gates_kernel<<<dim3(DVs / 8, 2, Bsz), 256>>>(Wdq, bdq, Wdk, bdk);

    int smq = 3 * QKV_STAGE * (int)sizeof(float);  // 56832 B
    cudaFuncSetAttribute(qkv_kernel, cudaFuncAttributeMaxDynamicSharedMemorySize, smq);
    qkv_kernel<<<dim3(DVs / 128, (Bsz * Ssz) / 128, 3), 256, smq>>>(
        X, Wq, bq, Wk, bk, Wv, bv);

    int sma = (ATTN_QS + 2 * ATTN_KST + 2 * ATTN_VST) * (int)sizeof(float);  // 106496 B
    cudaFuncSetAttribute(attn_kernel, cudaFuncAttributeMaxDynamicSharedMemorySize, sma);
    attn_kernel<<<dim3(Ssz / 128, Hs, Bsz), 256, sma>>>(amask, out);
}

// round 5
// speedup vs baseline: 4.1710x; 1.1149x over previous
#include <cuda_runtime.h>
#include <math.h>

#define Bsz 4
#define Ssz 2048
#define DVs 1024
#define Hs  16
#define Dhd 64
#define Tsz 64
#define DTs 768

#define LOG2E 1.4426950408889634f
#define QSCALE (0.125f * LOG2E)

// Scratch (allocation-free). q/k: tf32 bit patterns, pair-permuted d-layout.
// v: tf32 bit patterns, natural layout. q pre-scaled by 0.125*log2e.
__device__ float g_q[Bsz * Hs * Ssz * Dhd];
__device__ float g_k[Bsz * Hs * Ssz * Dhd];
__device__ float g_v[Bsz * Hs * Ssz * Dhd];
__device__ float g_gate[2][Bsz * DVs];
__device__ float g_pool[Bsz][DTs];

// ---------------------------------------------------------------------------
// helpers
// ---------------------------------------------------------------------------
__device__ __forceinline__ unsigned f2tf32(float x) {
    unsigned u;
    asm("cvt.rna.tf32.f32 %0, %1;" : "=r"(u) : "f"(x));
    return u;
}

__device__ __forceinline__ void mma_tf32(float* c, const unsigned* a, const unsigned* b) {
    asm volatile(
        "mma.sync.aligned.m16n8k8.row.col.f32.tf32.tf32.f32 "
        "{%0,%1,%2,%3}, {%4,%5,%6,%7}, {%8,%9}, {%0,%1,%2,%3};"
        : "+f"(c[0]), "+f"(c[1]), "+f"(c[2]), "+f"(c[3])
        : "r"(a[0]), "r"(a[1]), "r"(a[2]), "r"(a[3]), "r"(b[0]), "r"(b[1]));
}

__device__ __forceinline__ float shsel(float v0, float v1, int src, int odd) {
    float a = __shfl_sync(0xffffffffu, v0, src);
    float b = __shfl_sync(0xffffffffu, v1, src);
    return odd ? b : a;
}

__device__ __forceinline__ unsigned smem_u32(const void* p) {
    return (unsigned)__cvta_generic_to_shared(p);
}
__device__ __forceinline__ void cp16(unsigned dst, const void* src) {
    asm volatile("cp.async.cg.shared.global [%0], [%1], 16;" :: "r"(dst), "l"(src));
}
#define CP_COMMIT() asm volatile("cp.async.commit_group;")
#define CP_WAIT(n)  asm volatile("cp.async.wait_group %0;" :: "n"(n))

// ---------------------------------------------------------------------------
// Kernel 1a: masked-mean pool. grid(B), 256 threads.
// ---------------------------------------------------------------------------
__global__ void pool_kernel(const float* __restrict__ txt,
                            const float* __restrict__ tmask) {
    int b = blockIdx.x, tid = threadIdx.x;
    __shared__ float tm[Tsz];
    if (tid < Tsz) tm[tid] = tmask[b * Tsz + tid];
    __syncthreads();
    float ms = 0.f;
    #pragma unroll 8
    for (int t = 0; t < Tsz; t++) ms += tm[t];
    float inv = 1.f / ms;
    for (int d = tid; d < DTs; d += 256) {
        float acc = 0.f;
        #pragma unroll 8
        for (int t = 0; t < Tsz; t++)
            acc += txt[(b * Tsz + t) * DTs + d] * tm[t];
        g_pool[b][d] = acc * inv;
    }
}

// ---------------------------------------------------------------------------
// Kernel 1b: gates GEMV, warp-per-output. grid(DV/8, 2, B), 256 threads.
// ---------------------------------------------------------------------------
__global__ void gates_kernel(const float* __restrict__ Wdq, const float* __restrict__ bdq,
                             const float* __restrict__ Wdk, const float* __restrict__ bdk) {
    int which = blockIdx.y, b = blockIdx.z;
    const float* W    = which ? Wdk : Wdq;
    const float* bias = which ? bdk : bdq;
    int w = threadIdx.x >> 5, lane = threadIdx.x & 31;
    int n = blockIdx.x * 8 + w;

    float dot = 0.f;
    #pragma unroll 6
    for (int d = lane; d < DTs; d += 32)
        dot += g_pool[b][d] * W[d * DVs + n];
    #pragma unroll
    for (int off = 16; off; off >>= 1)
        dot += __shfl_xor_sync(0xffffffffu, dot, off);
    if (lane == 0) {
        float x = dot + bias[n];
        g_gate[which][b * DVs + n] = 1.f + 1.f / (1.f + __expf(-x));
    }
}

// ---------------------------------------------------------------------------
// Kernel 2: QKV projection, tf32 mma, 3-stage cp.async pipeline.
// Epilogue: bias+gate, cvt to tf32 bits; q/k written pair-permuted
// (stored[8b+2t+u] = orig[8b+t+4u]); q pre-scaled by 0.125*log2e.
// ---------------------------------------------------------------------------
#define QKV_STAGE 4736

__global__ void __launch_bounds__(256, 2) qkv_kernel(
        const float* __restrict__ X,
        const float* __restrict__ Wq, const float* __restrict__ bq,
        const float* __restrict__ Wk, const float* __restrict__ bk,
        const float* __restrict__ Wv, const float* __restrict__ bv) {
    extern __shared__ float smq[];
    int sel = blockIdx.z;
    const float* W    = sel == 0 ? Wq : (sel == 1 ? Wk : Wv);
    const float* bias = sel == 0 ? bq : (sel == 1 ? bk : bv);
    float* dst        = sel == 0 ? g_q : (sel == 1 ? g_k : g_v);

    int tid = threadIdx.x;
    int w = tid >> 5, lane = tid & 31;
    int tg = lane & 3, gid = lane >> 2;
    int warp_m = (w & 1) * 64, warp_n = (w >> 1) * 32;
    int m0 = blockIdx.y * 128, n0 = blockIdx.x * 128;

    int xc0 = tid, xc1 = tid + 256;
    int xr0 = xc0 >> 2, xq0 = (xc0 & 3) * 4;
    int xr1 = xc1 >> 2, xq1 = (xc1 & 3) * 4;
    int wk0 = xc0 >> 5, wn0 = (xc0 & 31) * 4;
    int wk1 = xc1 >> 5, wn1 = (xc1 & 31) * 4;

    const float* Xb = X + (size_t)m0 * DVs;

    float acc[4][4][4] = {};

    #pragma unroll
    for (int p = 0; p < 2; p++) {
        float* Xs = smq + p * QKV_STAGE;
        float* Ws = Xs + 128 * 20;
        int k0 = p * 16;
        cp16(smem_u32(Xs + xr0 * 20 + xq0), Xb + (size_t)xr0 * DVs + k0 + xq0);
        cp16(smem_u32(Xs + xr1 * 20 + xq1), Xb + (size_t)xr1 * DVs + k0 + xq1);
        cp16(smem_u32(Ws + wk0 * 136 + wn0), W + (size_t)(k0 + wk0) * DVs + n0 + wn0);
        cp16(smem_u32(Ws + wk1 * 136 + wn1), W + (size_t)(k0 + wk1) * DVs + n0 + wn1);
        CP_COMMIT();
    }

    int st = 0, st_ld = 2;
    for (int it = 0; it < 64; it++) {
        CP_WAIT(1);
        __syncthreads();

        if (it + 2 < 64) {
            float* Xs = smq + st_ld * QKV_STAGE;
            float* Ws = Xs + 128 * 20;
            int k0 = (it + 2) * 16;
            cp16(smem_u32(Xs + xr0 * 20 + xq0), Xb + (size_t)xr0 * DVs + k0 + xq0);
            cp16(smem_u32(Xs + xr1 * 20 + xq1), Xb + (size_t)xr1 * DVs + k0 + xq1);
            cp16(smem_u32(Ws + wk0 * 136 + wn0), W + (size_t)(k0 + wk0) * DVs + n0 + wn0);
            cp16(smem_u32(Ws + wk1 * 136 + wn1), W + (size_t)(k0 + wk1) * DVs + n0 + wn1);
        }
        CP_COMMIT();

        const float* Xs = smq + st * QKV_STAGE;
        const float* Ws = Xs + 128 * 20;

        #pragma unroll
        for (int ks = 0; ks < 2; ks++) {
            int kb = ks * 8;
            unsigned a[4][4];
            #pragma unroll
            for (int mi = 0; mi < 4; mi++) {
                int r = warp_m + mi * 16 + gid;
                a[mi][0] = f2tf32(Xs[r * 20 + kb + tg]);
                a[mi][1] = f2tf32(Xs[(r + 8) * 20 + kb + tg]);
                a[mi][2] = f2tf32(Xs[r * 20 + kb + tg + 4]);
                a[mi][3] = f2tf32(Xs[(r + 8) * 20 + kb + tg + 4]);
            }
            #pragma unroll
            for (int nj = 0; nj < 4; nj++) {
                unsigned bfr[2];
                bfr[0] = f2tf32(Ws[(kb + tg) * 136 + warp_n + nj * 8 + gid]);
                bfr[1] = f2tf32(Ws[(kb + tg + 4) * 136 + warp_n + nj * 8 + gid]);
                #pragma unroll
                for (int mi = 0; mi < 4; mi++)
                    mma_tf32(acc[mi][nj], a[mi], bfr);
            }
        }
        st = (st == 2) ? 0 : st + 1;
        st_ld = (st_ld == 2) ? 0 : st_ld + 1;
    }

    if (sel < 2) {
        // q/k: permuted scalar writes of tf32 bits
        float qs = (sel == 0) ? QSCALE : 1.f;
        const float* gate = g_gate[sel];
        int p0 = 2 * tg;
        int sc = (p0 < 4) ? 2 * p0 : 2 * p0 - 7;  // stored pos of orig p0; orig p0+1 -> sc+2
        #pragma unroll
        for (int nj = 0; nj < 4; nj++) {
            int colb = n0 + warp_n + nj * 8;
            int col = colb + p0;
            int h = colb >> 6, ddb = colb & 63;
            float b0 = bias[col], b1 = bias[col + 1];
            #pragma unroll
            for (int mi = 0; mi < 4; mi++) {
                int r0 = m0 + warp_m + mi * 16 + gid;
                int bb = r0 >> 11, s0 = r0 & 2047;
                float g0 = gate[bb * DVs + col];
                float g1 = gate[bb * DVs + col + 1];
                float v00 = (acc[mi][nj][0] + b0) * g0 * qs;
                float v01 = (acc[mi][nj][1] + b1) * g1 * qs;
                float v10 = (acc[mi][nj][2] + b0) * g0 * qs;
                float v11 = (acc[mi][nj][3] + b1) * g1 * qs;
                size_t base = ((size_t)bb * Hs + h) * Ssz;
                float* d0p = &dst[(base + s0) * Dhd + ddb];
                float* d1p = &dst[(base + s0 + 8) * Dhd + ddb];
                d0p[sc]     = __uint_as_float(f2tf32(v00));
                d0p[sc + 2] = __uint_as_float(f2tf32(v01));
                d1p[sc]     = __uint_as_float(f2tf32(v10));
                d1p[sc + 2] = __uint_as_float(f2tf32(v11));
            }
        }
    } else {
        // v: natural layout, tf32 bits, float2 writes
        #pragma unroll
        for (int nj = 0; nj < 4; nj++) {
            int col = n0 + warp_n + nj * 8 + 2 * tg;
            int h = col >> 6, dd = col & 63;
            float b0 = bias[col], b1 = bias[col + 1];
            #pragma unroll
            for (int mi = 0; mi < 4; mi++) {
                int r0 = m0 + warp_m + mi * 16 + gid;
                int bb = r0 >> 11, s0 = r0 & 2047;
                float2 o0 = {__uint_as_float(f2tf32(acc[mi][nj][0] + b0)),
                             __uint_as_float(f2tf32(acc[mi][nj][1] + b1))};
                float2 o1 = {__uint_as_float(f2tf32(acc[mi][nj][2] + b0)),
                             __uint_as_float(f2tf32(acc[mi][nj][3] + b1))};
                size_t base = ((size_t)bb * Hs + h) * Ssz;
                *(float2*)&dst[(base + s0) * Dhd + dd] = o0;
                *(float2*)&dst[(base + s0 + 8) * Dhd + dd] = o1;
            }
        }
    }
}

// ---------------------------------------------------------------------------
// Kernel 3: flash attention. All operands pre-converted tf32; Q/K pair-
// permuted -> LDS.64 fragment loads. Stride 72 (=8 mod 32): conflict-free.
// BQ=128, KV tile 64, 256 thr / 8 warps. grid (16, H, B).
// ---------------------------------------------------------------------------
#define ATTN_QS   (128 * 72)
#define ATTN_KST  (64 * 72)
#define ATTN_VST  (64 * 72)

__global__ void __launch_bounds__(256, 2) attn_kernel(
        const float* __restrict__ amask, float* __restrict__ out) {
    extern __shared__ float sma[];
    unsigned* Qs = (unsigned*)sma;                 // [128][72] tf32, permuted d
    float* Kbuf = sma + ATTN_QS;                   // [2][64][72] tf32, permuted d
    float* Vbuf = sma + ATTN_QS + 2 * ATTN_KST;    // [2][64][72] tf32, natural d

    int q0 = blockIdx.x * 128;
    int h = blockIdx.y, b = blockIdx.z;
    int tid = threadIdx.x;
    int w = tid >> 5, lane = tid & 31;
    int tg = lane & 3, gid = lane >> 2;
    int qr = w * 16;
    int tg2 = 2 * tg;

    const float* qbase = g_q + ((size_t)(b * Hs + h)) * Ssz * Dhd;
    const float* kbase = g_k + ((size_t)(b * Hs + h)) * Ssz * Dhd;
    const float* vbase = g_v + ((size_t)(b * Hs + h)) * Ssz * Dhd;

    int cr[4], cq[4];
    #pragma unroll
    for (int i = 0; i < 4; i++) {
        int c = tid + i * 256;
        cr[i] = c >> 4;
        cq[i] = (c & 15) * 4;
    }

    // load Q tile (already tf32 bits, permuted, pre-scaled)
    #pragma unroll
    for (int it = 0; it < 8; it++) {
        int idx = it * 256 + tid;
        int r = idx >> 4, c4 = (idx & 15) * 4;
        *(uint4*)&Qs[r * 72 + c4] = *(const uint4*)&qbase[(size_t)(q0 + r) * Dhd + c4];
    }

    #pragma unroll
    for (int p = 0; p < 2; p++) {
        float* Kr = Kbuf + p * ATTN_KST;
        float* Vr = Vbuf + p * ATTN_VST;
        int kr0 = p * 64;
        #pragma unroll
        for (int i = 0; i < 4; i++) {
            cp16(smem_u32(Kr + cr[i] * 72 + cq[i]), kbase + (size_t)(kr0 + cr[i]) * Dhd + cq[i]);
            cp16(smem_u32(Vr + cr[i] * 72 + cq[i]), vbase + (size_t)(kr0 + cr[i]) * Dhd + cq[i]);
        }
        CP_COMMIT();
    }

    float o[8][4] = {};
    float m0 = -1e30f, m1 = -1e30f, l0 = 0.f, l1 = 0.f;

    int src0 = (lane & 28) | (tg >> 1);
    int src1 = src0 + 2;
    int odd = tg & 1;

    for (int kt = 0; kt < Ssz / 64; kt++) {
        int kr0 = kt * 64;
        int buf = kt & 1;
        const unsigned* Kr = (const unsigned*)(Kbuf + buf * ATTN_KST);
        const unsigned* Vr = (const unsigned*)(Vbuf + buf * ATTN_VST);

        CP_WAIT(1);
        __syncthreads();

        // S = Q K^T : LDS.64 fragment loads (paired k via permuted layout)
        float s[8][4] = {};
        #pragma unroll
        for (int ks = 0; ks < 8; ks++) {
            int kb = ks * 8;
            uint2 a01 = *(const uint2*)&Qs[(qr + gid) * 72 + kb + tg2];
            uint2 a23 = *(const uint2*)&Qs[(qr + gid + 8) * 72 + kb + tg2];
            unsigned a[4] = {a01.x, a23.x, a01.y, a23.y};
            #pragma unroll
            for (int j = 0; j < 8; j++) {
                uint2 bb = *(const uint2*)&Kr[(j * 8 + gid) * 72 + kb + tg2];
                unsigned bfr[2] = {bb.x, bb.y};
                mma_tf32(s[j], a, bfr);
            }
        }

        // mask (x log2e) + online softmax in base-2 domain
        float mx0 = -1e30f, mx1 = -1e30f;
        #pragma unroll
        for (int j = 0; j < 8; j++) {
            float2 mk = *(const float2*)&amask[b * Ssz + kr0 + j * 8 + tg2];
            float mk0 = mk.x * LOG2E, mk1 = mk.y * LOG2E;
            s[j][0] += mk0; s[j][1] += mk1;
            s[j][2] += mk0; s[j][3] += mk1;
            mx0 = fmaxf(mx0, fmaxf(s[j][0], s[j][1]));
            mx1 = fmaxf(mx1, fmaxf(s[j][2], s[j][3]));
        }
        #pragma unroll
        for (int off = 1; off <= 2; off <<= 1) {
            mx0 = fmaxf(mx0, __shfl_xor_sync(0xffffffffu, mx0, off));
            mx1 = fmaxf(mx1, __shfl_xor_sync(0xffffffffu, mx1, off));
        }
        float mn0 = fmaxf(m0, mx0), mn1 = fmaxf(m1, mx1);
        float al0 = exp2f(m0 - mn0), al1 = exp2f(m1 - mn1);
        m0 = mn0; m1 = mn1;

        float rs0 = 0.f, rs1 = 0.f;
        #pragma unroll
        for (int j = 0; j < 8; j++) {
            s[j][0] = exp2f(s[j][0] - mn0);
            s[j][1] = exp2f(s[j][1] - mn0);
            s[j][2] = exp2f(s[j][2] - mn1);
            s[j][3] = exp2f(s[j][3] - mn1);
            rs0 += s[j][0] + s[j][1];
            rs1 += s[j][2] + s[j][3];
        }
        #pragma unroll
        for (int off = 1; off <= 2; off <<= 1) {
            rs0 += __shfl_xor_sync(0xffffffffu, rs0, off);
            rs1 += __shfl_xor_sync(0xffffffffu, rs1, off);
        }
        l0 = l0 * al0 + rs0;
        l1 = l1 * al1 + rs1;

        #pragma unroll
        for (int dj = 0; dj < 8; dj++) {
            o[dj][0] *= al0; o[dj][1] *= al0;
            o[dj][2] *= al1; o[dj][3] *= al1;
        }

        // O += P V (P via shuffle C->A conversion; V already tf32)
        #pragma unroll
        for (int j = 0; j < 8; j++) {
            unsigned pa[4];
            pa[0] = f2tf32(shsel(s[j][0], s[j][1], src0, odd));
            pa[2] = f2tf32(shsel(s[j][0], s[j][1], src1, odd));
            pa[1] = f2tf32(shsel(s[j][2], s[j][3], src0, odd));
            pa[3] = f2tf32(shsel(s[j][2], s[j][3], src1, odd));
            #pragma unroll
            for (int dj = 0; dj < 8; dj++) {
                unsigned bfr[2];
                bfr[0] = Vr[(j * 8 + tg) * 72 + dj * 8 + gid];
                bfr[1] = Vr[(j * 8 + tg + 4) * 72 + dj * 8 + gid];
                mma_tf32(o[dj], pa, bfr);
            }
        }

        __syncthreads();
        if (kt + 2 < Ssz / 64) {
            float* Kw = Kbuf + buf * ATTN_KST;
            float* Vw = Vbuf + buf * ATTN_VST;
            int kn0 = (kt + 2) * 64;
            #pragma unroll
            for (int i = 0; i < 4; i++) {
                cp16(smem_u32(Kw + cr[i] * 72 + cq[i]), kbase + (size_t)(kn0 + cr[i]) * Dhd + cq[i]);
                cp16(smem_u32(Vw + cr[i] * 72 + cq[i]), vbase + (size_t)(kn0 + cr[i]) * Dhd + cq[i]);
            }
        }
        CP_COMMIT();
    }

    float inv0 = 1.f / l0, inv1 = 1.f / l1;
    int r0 = q0 + qr + gid, r1 = r0 + 8;
    #pragma unroll
    for (int dj = 0; dj < 8; dj++) {
        int col = h * Dhd + dj * 8 + tg2;
        float2 o0 = {o[dj][0] * inv0, o[dj][1] * inv0};
        float2 o1 = {o[dj][2] * inv1, o[dj][3] * inv1};
        *(float2*)&out[((size_t)b * Ssz + r0) * DVs + col] = o0;
        *(float2*)&out[((size_t)b * Ssz + r1) * DVs + col] = o1;
    }
}

// ---------------------------------------------------------------------------
extern "C" void kernel_launch(void* const* d_in, const int* in_sizes, int n_in,
                              void* d_out, int out_size) {
    const float* X     = (const float*)d_in[0];
    const float* amask = (const float*)d_in[1];
    const float* txt   = (const float*)d_in[2];
    const float* tmask = (const float*)d_in[3];
    const float* Wq  = (const float*)d_in[4];
    const float* bq  = (const float*)d_in[5];
    const float* Wk  = (const float*)d_in[6];
    const float* bk  = (const float*)d_in[7];
    const float* Wv  = (const float*)d_in[8];
    const float* bv  = (const float*)d_in[9];
    const float* Wdq = (const float*)d_in[10];
    const float* bdq = (const float*)d_in[11];
    const float* Wdk = (const float*)d_in[12];
    const float* bdk = (const float*)d_in[13];
    float* out = (float*)d_out;

    pool_kernel<<<Bsz, 256>>>(txt, tmask);
    gates_kernel<<<dim3(DVs / 8, 2, Bsz), 256>>>(Wdq, bdq, Wdk, bdk);

    int smq = 3 * QKV_STAGE * (int)sizeof(float);  // 56832 B
    cudaFuncSetAttribute(qkv_kernel, cudaFuncAttributeMaxDynamicSharedMemorySize, smq);
    qkv_kernel<<<dim3(DVs / 128, (Bsz * Ssz) / 128, 3), 256, smq>>>(
        X, Wq, bq, Wk, bk, Wv, bv);

    int sma = (ATTN_QS + 2 * ATTN_KST + 2 * ATTN_VST) * (int)sizeof(float);  // 110592 B
    cudaFuncSetAttribute(attn_kernel, cudaFuncAttributeMaxDynamicSharedMemorySize, sma);
    attn_kernel<<<dim3(Ssz / 128, Hs, Bsz), 256, sma>>>(amask, out);
}

// round 8
// speedup vs baseline: 4.3373x; 1.0399x over previous
#include <cuda_runtime.h>
#include <math.h>

#define Bsz 4
#define Ssz 2048
#define DVs 1024
#define Hs  16
#define Dhd 64
#define Tsz 64
#define DTs 768

#define LOG2E 1.4426950408889634f
#define QSCALE (0.125f * LOG2E)

// Scratch (allocation-free).
// g_q/g_k: [B,H,S,Dh] tf32 bits, d pair-permuted within groups of 8; q pre-scaled.
// g_v:     [B,H,Dh,S] tf32 bits, S pair-permuted within groups of 8.
// g_xt:    X pre-converted to tf32 bits, k pair-permuted within groups of 8.
// g_wt:    Wq/Wk/Wv pre-converted to tf32 bits, k-rows pair-permuted.
__device__ float g_q[Bsz * Hs * Ssz * Dhd];
__device__ float g_k[Bsz * Hs * Ssz * Dhd];
__device__ float g_v[Bsz * Hs * Ssz * Dhd];
__device__ float g_gate[2][Bsz * DVs];
__device__ float g_pool[Bsz][DTs];
__device__ float g_xt[Bsz * Ssz * DVs];
__device__ float g_wt[3][DVs * DVs];

// ---------------------------------------------------------------------------
// helpers
// ---------------------------------------------------------------------------
__device__ __forceinline__ unsigned f2tf32(float x) {
    unsigned u;
    asm("cvt.rna.tf32.f32 %0, %1;" : "=r"(u) : "f"(x));
    return u;
}

__device__ __forceinline__ void mma_tf32(float* c, const unsigned* a, const unsigned* b) {
    asm volatile(
        "mma.sync.aligned.m16n8k8.row.col.f32.tf32.tf32.f32 "
        "{%0,%1,%2,%3}, {%4,%5,%6,%7}, {%8,%9}, {%0,%1,%2,%3};"
        : "+f"(c[0]), "+f"(c[1]), "+f"(c[2]), "+f"(c[3])
        : "r"(a[0]), "r"(a[1]), "r"(a[2]), "r"(a[3]), "r"(b[0]), "r"(b[1]));
}

__device__ __forceinline__ float shsel(float v0, float v1, int src, int odd) {
    float a = __shfl_sync(0xffffffffu, v0, src);
    float b = __shfl_sync(0xffffffffu, v1, src);
    return odd ? b : a;
}

__device__ __forceinline__ unsigned smem_u32(const void* p) {
    return (unsigned)__cvta_generic_to_shared(p);
}
__device__ __forceinline__ void cp16(unsigned dst, const void* src) {
    asm volatile("cp.async.cg.shared.global [%0], [%1], 16;" :: "r"(dst), "l"(src));
}
#define CP_COMMIT() asm volatile("cp.async.commit_group;")
#define CP_WAIT(n)  asm volatile("cp.async.wait_group %0;" :: "n"(n))

// ---------------------------------------------------------------------------
// Kernel 0a: convert X -> tf32 bits, k pair-permuted within groups of 8.
// ---------------------------------------------------------------------------
__global__ void cvtx_kernel(const float* __restrict__ X) {
    size_t g = (size_t)blockIdx.x * blockDim.x + threadIdx.x;
    const float4* in = (const float4*)(X + g * 8);
    float4 i0 = in[0], i1 = in[1];
    uint4 o0, o1;
    o0.x = f2tf32(i0.x); o0.y = f2tf32(i1.x); o0.z = f2tf32(i0.y); o0.w = f2tf32(i1.y);
    o1.x = f2tf32(i0.z); o1.y = f2tf32(i1.z); o1.z = f2tf32(i0.w); o1.w = f2tf32(i1.w);
    uint4* out = (uint4*)(g_xt + g * 8);
    out[0] = o0;
    out[1] = o1;
}

// ---------------------------------------------------------------------------
// Kernel 0b: convert Wq/Wk/Wv -> tf32 bits, k-rows pair-permuted.
// ---------------------------------------------------------------------------
__global__ void cvtw_kernel(const float* __restrict__ Wq,
                            const float* __restrict__ Wk,
                            const float* __restrict__ Wv) {
    size_t idx = (size_t)blockIdx.x * blockDim.x + threadIdx.x;
    int sel = (int)(idx / (DVs * DVs / 4));
    size_t rem = idx % (DVs * DVs / 4);
    int k = (int)(rem / (DVs / 4));
    int c4 = (int)(rem % (DVs / 4)) * 4;
    const float* W = sel == 0 ? Wq : (sel == 1 ? Wk : Wv);
    int j = k & 7;
    int ks = (k & ~7) | (j < 4 ? 2 * j : 2 * j - 7);
    float4 v = *(const float4*)&W[(size_t)k * DVs + c4];
    uint4 o = {f2tf32(v.x), f2tf32(v.y), f2tf32(v.z), f2tf32(v.w)};
    *(uint4*)&g_wt[sel][(size_t)ks * DVs + c4] = o;
}

// ---------------------------------------------------------------------------
// Kernel 1a: masked-mean pool. grid(B), 256 threads.
// ---------------------------------------------------------------------------
__global__ void pool_kernel(const float* __restrict__ txt,
                            const float* __restrict__ tmask) {
    int b = blockIdx.x, tid = threadIdx.x;
    __shared__ float tm[Tsz];
    if (tid < Tsz) tm[tid] = tmask[b * Tsz + tid];
    __syncthreads();
    float ms = 0.f;
    #pragma unroll 8
    for (int t = 0; t < Tsz; t++) ms += tm[t];
    float inv = 1.f / ms;
    for (int d = tid; d < DTs; d += 256) {
        float acc = 0.f;
        #pragma unroll 8
        for (int t = 0; t < Tsz; t++)
            acc += txt[(b * Tsz + t) * DTs + d] * tm[t];
        g_pool[b][d] = acc * inv;
    }
}

// ---------------------------------------------------------------------------
// Kernel 1b: gates GEMV, warp-per-output. grid(DV/8, 2, B), 256 threads.
// ---------------------------------------------------------------------------
__global__ void gates_kernel(const float* __restrict__ Wdq, const float* __restrict__ bdq,
                             const float* __restrict__ Wdk, const float* __restrict__ bdk) {
    int which = blockIdx.y, b = blockIdx.z;
    const float* W    = which ? Wdk : Wdq;
    const float* bias = which ? bdk : bdq;
    int w = threadIdx.x >> 5, lane = threadIdx.x & 31;
    int n = blockIdx.x * 8 + w;

    float dot = 0.f;
    #pragma unroll 6
    for (int d = lane; d < DTs; d += 32)
        dot += g_pool[b][d] * W[d * DVs + n];
    #pragma unroll
    for (int off = 16; off; off >>= 1)
        dot += __shfl_xor_sync(0xffffffffu, dot, off);
    if (lane == 0) {
        float x = dot + bias[n];
        g_gate[which][b * DVs + n] = 1.f + 1.f / (1.f + __expf(-x));
    }
}

// ---------------------------------------------------------------------------
// Kernel 2: QKV projection, tf32 mma, 3-stage cp.async pipeline.
// Inputs pre-converted/permuted: zero cvts in the mainloop; A-frags LDS.64.
// ---------------------------------------------------------------------------
#define QKV_STAGE 5184

__global__ void __launch_bounds__(256, 2) qkv_kernel(
        const float* __restrict__ bq,
        const float* __restrict__ bk,
        const float* __restrict__ bv) {
    extern __shared__ float smq[];
    int sel = blockIdx.z;
    const float* W    = g_wt[sel];
    const float* bias = sel == 0 ? bq : (sel == 1 ? bk : bv);
    float* dst        = sel == 0 ? g_q : (sel == 1 ? g_k : g_v);

    int tid = threadIdx.x;
    int w = tid >> 5, lane = tid & 31;
    int tg = lane & 3, gid = lane >> 2;
    int tg2 = 2 * tg;
    int warp_m = (w & 1) * 64, warp_n = (w >> 1) * 32;
    int m0 = blockIdx.y * 128, n0 = blockIdx.x * 128;

    int xc0 = tid, xc1 = tid + 256;
    int xr0 = xc0 >> 2, xq0 = (xc0 & 3) * 4;
    int xr1 = xc1 >> 2, xq1 = (xc1 & 3) * 4;
    int wk0 = xc0 >> 5, wn0 = (xc0 & 31) * 4;
    int wk1 = xc1 >> 5, wn1 = (xc1 & 31) * 4;

    const float* Xb = g_xt + (size_t)m0 * DVs;

    float acc[4][4][4] = {};

    #pragma unroll
    for (int p = 0; p < 2; p++) {
        float* Xs = smq + p * QKV_STAGE;
        float* Ws = Xs + 128 * 24;
        int k0 = p * 16;
        cp16(smem_u32(Xs + xr0 * 24 + xq0), Xb + (size_t)xr0 * DVs + k0 + xq0);
        cp16(smem_u32(Xs + xr1 * 24 + xq1), Xb + (size_t)xr1 * DVs + k0 + xq1);
        cp16(smem_u32(Ws + wk0 * 132 + wn0), W + (size_t)(k0 + wk0) * DVs + n0 + wn0);
        cp16(smem_u32(Ws + wk1 * 132 + wn1), W + (size_t)(k0 + wk1) * DVs + n0 + wn1);
        CP_COMMIT();
    }

    int st = 0, st_ld = 2;
    for (int it = 0; it < 64; it++) {
        CP_WAIT(1);
        __syncthreads();

        if (it + 2 < 64) {
            float* Xs = smq + st_ld * QKV_STAGE;
            float* Ws = Xs + 128 * 24;
            int k0 = (it + 2) * 16;
            cp16(smem_u32(Xs + xr0 * 24 + xq0), Xb + (size_t)xr0 * DVs + k0 + xq0);
            cp16(smem_u32(Xs + xr1 * 24 + xq1), Xb + (size_t)xr1 * DVs + k0 + xq1);
            cp16(smem_u32(Ws + wk0 * 132 + wn0), W + (size_t)(k0 + wk0) * DVs + n0 + wn0);
            cp16(smem_u32(Ws + wk1 * 132 + wn1), W + (size_t)(k0 + wk1) * DVs + n0 + wn1);
        }
        CP_COMMIT();

        const unsigned* Xs = (const unsigned*)(smq + st * QKV_STAGE);
        const unsigned* Ws = Xs + 128 * 24;

        #pragma unroll
        for (int ks = 0; ks < 2; ks++) {
            int kb = ks * 8;
            unsigned a[4][4];
            #pragma unroll
            for (int mi = 0; mi < 4; mi++) {
                int r = warp_m + mi * 16 + gid;
                uint2 u0 = *(const uint2*)&Xs[r * 24 + kb + tg2];
                uint2 u1 = *(const uint2*)&Xs[(r + 8) * 24 + kb + tg2];
                a[mi][0] = u0.x; a[mi][1] = u1.x; a[mi][2] = u0.y; a[mi][3] = u1.y;
            }
            #pragma unroll
            for (int nj = 0; nj < 4; nj++) {
                unsigned bfr[2];
                bfr[0] = Ws[(kb + tg2) * 132 + warp_n + nj * 8 + gid];
                bfr[1] = Ws[(kb + tg2 + 1) * 132 + warp_n + nj * 8 + gid];
                #pragma unroll
                for (int mi = 0; mi < 4; mi++)
                    mma_tf32(acc[mi][nj], a[mi], bfr);
            }
        }
        st = (st == 2) ? 0 : st + 1;
        st_ld = (st_ld == 2) ? 0 : st_ld + 1;
    }

    if (sel < 2) {
        // q/k: [B,H,S,Dh], d pair-permuted; q pre-scaled by 0.125*log2e
        float qs = (sel == 0) ? QSCALE : 1.f;
        const float* gate = g_gate[sel];
        int p0 = tg2;
        int sc = (p0 < 4) ? 2 * p0 : 2 * p0 - 7;
        #pragma unroll
        for (int nj = 0; nj < 4; nj++) {
            int colb = n0 + warp_n + nj * 8;
            int col = colb + p0;
            int h = colb >> 6, ddb = colb & 63;
            float b0 = bias[col], b1 = bias[col + 1];
            #pragma unroll
            for (int mi = 0; mi < 4; mi++) {
                int r0 = m0 + warp_m + mi * 16 + gid;
                int bb = r0 >> 11, s0 = r0 & 2047;
                float g0 = gate[bb * DVs + col];
                float g1 = gate[bb * DVs + col + 1];
                float v00 = (acc[mi][nj][0] + b0) * g0 * qs;
                float v01 = (acc[mi][nj][1] + b1) * g1 * qs;
                float v10 = (acc[mi][nj][2] + b0) * g0 * qs;
                float v11 = (acc[mi][nj][3] + b1) * g1 * qs;
                size_t base = ((size_t)bb * Hs + h) * Ssz;
                float* d0p = &dst[(base + s0) * Dhd + ddb];
                float* d1p = &dst[(base + s0 + 8) * Dhd + ddb];
                d0p[sc]     = __uint_as_float(f2tf32(v00));
                d0p[sc + 2] = __uint_as_float(f2tf32(v01));
                d1p[sc]     = __uint_as_float(f2tf32(v10));
                d1p[sc + 2] = __uint_as_float(f2tf32(v11));
            }
        }
    } else {
        // v: transposed [B,H,Dh,S], s pair-permuted within groups of 8
        int sp = (gid < 4) ? 2 * gid : 2 * gid - 7;
        #pragma unroll
        for (int nj = 0; nj < 4; nj++) {
            int col = n0 + warp_n + nj * 8 + tg2;
            int h = col >> 6, dd = col & 63;
            float b0 = bias[col], b1 = bias[col + 1];
            #pragma unroll
            for (int mi = 0; mi < 4; mi++) {
                int r0 = m0 + warp_m + mi * 16 + gid;
                int bb = r0 >> 11, s0 = r0 & 2047;
                int sb = s0 - gid;
                size_t row0 = ((size_t)bb * Hs + h) * Dhd + dd;
                dst[row0 * Ssz + sb + sp] =
                    __uint_as_float(f2tf32(acc[mi][nj][0] + b0));
                dst[(row0 + 1) * Ssz + sb + sp] =
                    __uint_as_float(f2tf32(acc[mi][nj][1] + b1));
                dst[row0 * Ssz + sb + 8 + sp] =
                    __uint_as_float(f2tf32(acc[mi][nj][2] + b0));
                dst[(row0 + 1) * Ssz + sb + 8 + sp] =
                    __uint_as_float(f2tf32(acc[mi][nj][3] + b1));
            }
        }
    }
}

// ---------------------------------------------------------------------------
// Kernel 3: flash attention. Q/K d-permuted, V transposed+s-permuted:
// all three mma fragment loads are LDS.64. grid (16, H, B), 256 thr.
// ---------------------------------------------------------------------------
#define ATTN_QS   (128 * 72)
#define ATTN_KST  (64 * 72)
#define ATTN_VST  (64 * 72)

__global__ void __launch_bounds__(256, 2) attn_kernel(
        const float* __restrict__ amask, float* __restrict__ out) {
    extern __shared__ float sma[];
    unsigned* Qs = (unsigned*)sma;                 // [128 q][72] permuted d
    float* Kbuf = sma + ATTN_QS;                   // [2][64 kv][72] permuted d
    float* Vbuf = sma + ATTN_QS + 2 * ATTN_KST;    // [2][64 d][72] permuted kv

    int q0 = blockIdx.x * 128;
    int h = blockIdx.y, b = blockIdx.z;
    int tid = threadIdx.x;
    int w = tid >> 5, lane = tid & 31;
    int tg = lane & 3, gid = lane >> 2;
    int qr = w * 16;
    int tg2 = 2 * tg;

    const float* qbase = g_q + ((size_t)(b * Hs + h)) * Ssz * Dhd;
    const float* kbase = g_k + ((size_t)(b * Hs + h)) * Ssz * Dhd;
    const float* vbase = g_v + ((size_t)(b * Hs + h)) * Dhd * Ssz;

    int cr[4], cq[4];
    #pragma unroll
    for (int i = 0; i < 4; i++) {
        int c = tid + i * 256;
        cr[i] = c >> 4;
        cq[i] = (c & 15) * 4;
    }

    #pragma unroll
    for (int it = 0; it < 8; it++) {
        int idx = it * 256 + tid;
        int r = idx >> 4, c4 = (idx & 15) * 4;
        *(uint4*)&Qs[r * 72 + c4] = *(const uint4*)&qbase[(size_t)(q0 + r) * Dhd + c4];
    }

    #pragma unroll
    for (int p = 0; p < 2; p++) {
        float* Kr = Kbuf + p * ATTN_KST;
        float* Vr = Vbuf + p * ATTN_VST;
        int kr0 = p * 64;
        #pragma unroll
        for (int i = 0; i < 4; i++) {
            cp16(smem_u32(Kr + cr[i] * 72 + cq[i]), kbase + (size_t)(kr0 + cr[i]) * Dhd + cq[i]);
            cp16(smem_u32(Vr + cr[i] * 72 + cq[i]), vbase + (size_t)cr[i] * Ssz + kr0 + cq[i]);
        }
        CP_COMMIT();
    }

    float o[8][4] = {};
    float m0 = -1e30f, m1 = -1e30f, l0 = 0.f, l1 = 0.f;

    int src0 = (lane & 28) | (tg >> 1);
    int src1 = src0 + 2;
    int odd = tg & 1;

    for (int kt = 0; kt < Ssz / 64; kt++) {
        int kr0 = kt * 64;
        int buf = kt & 1;
        const unsigned* Kr = (const unsigned*)(Kbuf + buf * ATTN_KST);
        const unsigned* Vr = (const unsigned*)(Vbuf + buf * ATTN_VST);

        CP_WAIT(1);
        __syncthreads();

        // S = Q K^T
        float s[8][4] = {};
        #pragma unroll
        for (int ks = 0; ks < 8; ks++) {
            int kb = ks * 8;
            uint2 a01 = *(const uint2*)&Qs[(qr + gid) * 72 + kb + tg2];
            uint2 a23 = *(const uint2*)&Qs[(qr + gid + 8) * 72 + kb + tg2];
            unsigned a[4] = {a01.x, a23.x, a01.y, a23.y};
            #pragma unroll
            for (int j = 0; j < 8; j++) {
                uint2 bb = *(const uint2*)&Kr[(j * 8 + gid) * 72 + kb + tg2];
                unsigned bfr[2] = {bb.x, bb.y};
                mma_tf32(s[j], a, bfr);
            }
        }

        // mask (x log2e) + online softmax (base-2)
        float mx0 = -1e30f, mx1 = -1e30f;
        #pragma unroll
        for (int j = 0; j < 8; j++) {
            float2 mk = *(const float2*)&amask[b * Ssz + kr0 + j * 8 + tg2];
            float mk0 = mk.x * LOG2E, mk1 = mk.y * LOG2E;
            s[j][0] += mk0; s[j][1] += mk1;
            s[j][2] += mk0; s[j][3] += mk1;
            mx0 = fmaxf(mx0, fmaxf(s[j][0], s[j][1]));
            mx1 = fmaxf(mx1, fmaxf(s[j][2], s[j][3]));
        }
        #pragma unroll
        for (int off = 1; off <= 2; off <<= 1) {
            mx0 = fmaxf(mx0, __shfl_xor_sync(0xffffffffu, mx0, off));
            mx1 = fmaxf(mx1, __shfl_xor_sync(0xffffffffu, mx1, off));
        }
        float mn0 = fmaxf(m0, mx0), mn1 = fmaxf(m1, mx1);
        float al0 = exp2f(m0 - mn0), al1 = exp2f(m1 - mn1);
        m0 = mn0; m1 = mn1;

        float rs0 = 0.f, rs1 = 0.f;
        #pragma unroll
        for (int j = 0; j < 8; j++) {
            s[j][0] = exp2f(s[j][0] - mn0);
            s[j][1] = exp2f(s[j][1] - mn0);
            s[j][2] = exp2f(s[j][2] - mn1);
            s[j][3] = exp2f(s[j][3] - mn1);
            rs0 += s[j][0] + s[j][1];
            rs1 += s[j][2] + s[j][3];
        }
        #pragma unroll
        for (int off = 1; off <= 2; off <<= 1) {
            rs0 += __shfl_xor_sync(0xffffffffu, rs0, off);
            rs1 += __shfl_xor_sync(0xffffffffu, rs1, off);
        }
        l0 = l0 * al0 + rs0;
        l1 = l1 * al1 + rs1;

        #pragma unroll
        for (int dj = 0; dj < 8; dj++) {
            o[dj][0] *= al0; o[dj][1] *= al0;
            o[dj][2] *= al1; o[dj][3] *= al1;
        }

        // O += P V (P via shuffle C->A; V fragment LDS.64)
        #pragma unroll
        for (int j = 0; j < 8; j++) {
            unsigned pa[4];
            pa[0] = f2tf32(shsel(s[j][0], s[j][1], src0, odd));
            pa[2] = f2tf32(shsel(s[j][0], s[j][1], src1, odd));
            pa[1] = f2tf32(shsel(s[j][2], s[j][3], src0, odd));
            pa[3] = f2tf32(shsel(s[j][2], s[j][3], src1, odd));
            #pragma unroll
            for (int dj = 0; dj < 8; dj++) {
                uint2 vv = *(const uint2*)&Vr[(dj * 8 + gid) * 72 + j * 8 + tg2];
                unsigned bfr[2] = {vv.x, vv.y};
                mma_tf32(o[dj], pa, bfr);
            }
        }

        __syncthreads();
        if (kt + 2 < Ssz / 64) {
            float* Kw = Kbuf + buf * ATTN_KST;
            float* Vw = Vbuf + buf * ATTN_VST;
            int kn0 = (kt + 2) * 64;
            #pragma unroll
            for (int i = 0; i < 4; i++) {
                cp16(smem_u32(Kw + cr[i] * 72 + cq[i]), kbase + (size_t)(kn0 + cr[i]) * Dhd + cq[i]);
                cp16(smem_u32(Vw + cr[i] * 72 + cq[i]), vbase + (size_t)cr[i] * Ssz + kn0 + cq[i]);
            }
        }
        CP_COMMIT();
    }

    float inv0 = 1.f / l0, inv1 = 1.f / l1;
    int r0 = q0 + qr + gid, r1 = r0 + 8;
    #pragma unroll
    for (int dj = 0; dj < 8; dj++) {
        int col = h * Dhd + dj * 8 + tg2;
        float2 o0 = {o[dj][0] * inv0, o[dj][1] * inv0};
        float2 o1 = {o[dj][2] * inv1, o[dj][3] * inv1};
        *(float2*)&out[((size_t)b * Ssz + r0) * DVs + col] = o0;
        *(float2*)&out[((size_t)b * Ssz + r1) * DVs + col] = o1;
    }
}

// ---------------------------------------------------------------------------
extern "C" void kernel_launch(void* const* d_in, const int* in_sizes, int n_in,
                              void* d_out, int out_size) {
    const float* X     = (const float*)d_in[0];
    const float* amask = (const float*)d_in[1];
    const float* txt   = (const float*)d_in[2];
    const float* tmask = (const float*)d_in[3];
    const float* Wq  = (const float*)d_in[4];
    const float* bq  = (const float*)d_in[5];
    const float* Wk  = (const float*)d_in[6];
    const float* bk  = (const float*)d_in[7];
    const float* Wv  = (const float*)d_in[8];
    const float* bv  = (const float*)d_in[9];
    const float* Wdq = (const float*)d_in[10];
    const float* bdq = (const float*)d_in[11];
    const float* Wdk = (const float*)d_in[12];
    const float* bdk = (const float*)d_in[13];
    float* out = (float*)d_out;

    pool_kernel<<<Bsz, 256>>>(txt, tmask);
    gates_kernel<<<dim3(DVs / 8, 2, Bsz), 256>>>(Wdq, bdq, Wdk, bdk);

    cvtx_kernel<<<(Bsz * Ssz * DVs / 8) / 256, 256>>>(X);
    cvtw_kernel<<<(3 * DVs * DVs / 4) / 256, 256>>>(Wq, Wk, Wv);

    int smq = 3 * QKV_STAGE * (int)sizeof(float);  // 62208 B
    cudaFuncSetAttribute(qkv_kernel, cudaFuncAttributeMaxDynamicSharedMemorySize, smq);
    qkv_kernel<<<dim3(DVs / 128, (Bsz * Ssz) / 128, 3), 256, smq>>>(bq, bk, bv);

    int sma = (ATTN_QS + 2 * ATTN_KST + 2 * ATTN_VST) * (int)sizeof(float);  // 110592 B
    cudaFuncSetAttribute(attn_kernel, cudaFuncAttributeMaxDynamicSharedMemorySize, sma);
    attn_kernel<<<dim3(Ssz / 128, Hs, Bsz), 256, sma>>>(amask, out);
}